// round 1
// baseline (speedup 1.0000x reference)
#include <cuda_runtime.h>
#include <cfloat>

// Shapes (fixed per problem)
#define B_   256
#define P_   128
#define K_   512
#define HE_  1024
#define HF2_ 1024
#define HID_ 64
#define KB_  32
#define EMB_ 1536   // K_ + HF2_

__global__ __launch_bounds__(256, 2)
void attn_fused(const float* __restrict__ query,
                const float* __restrict__ keys,
                const float* __restrict__ frame,
                const int*   __restrict__ mask,
                const float* __restrict__ W1,
                const float* __restrict__ W2,
                float* __restrict__ out) {
    __shared__ float sA[KB_][P_];     // keys tile, transposed [k][p] : 16 KB
    __shared__ float sB[KB_][HID_];   // W1k tile [k][h]             : 8 KB
    __shared__ float sQF[HID_];
    __shared__ float sQFp[4][HID_];
    __shared__ float sW2[HID_];
    __shared__ float sScore[P_];

    const int b = blockIdx.x;
    const int t = threadIdx.x;
    const float* keyb = keys  + (size_t)b * P_ * K_;
    const float* qb   = query + (size_t)b * HE_;
    const float* fb   = frame + (size_t)b * HF2_;

    // ---- qf[h] = query[b] @ W1q + frame[b] @ W1f  (shared across all p) ----
    {
        const int part = t >> 6;          // 0..3 (two query halves, two frame halves)
        const int h    = t & 63;
        const float* src = (part < 2) ? (qb + part * 512) : (fb + (part - 2) * 512);
        const float* w   = W1 + (size_t)(K_ + part * 512) * HID_ + h;
        float acc = 0.f;
        #pragma unroll 16
        for (int d = 0; d < 512; d++)
            acc = fmaf(src[d], w[(size_t)d * HID_], acc);
        sQFp[part][h] = acc;
        if (t < HID_) sW2[t] = W2[t];
    }
    __syncthreads();
    if (t < HID_) sQF[t] = sQFp[0][t] + sQFp[1][t] + sQFp[2][t] + sQFp[3][t];

    // ---- main GEMM: acc[p_tile][h_tile] = keys[b] @ W1k ----
    const int tx = t & 15;   // h block of 4
    const int ty = t >> 4;   // p block of 8
    float acc[8][4];
    #pragma unroll
    for (int i = 0; i < 8; i++)
        #pragma unroll
        for (int j = 0; j < 4; j++) acc[i][j] = 0.f;

    const int prow = t >> 1;        // loader: 2 threads per p-row
    const int half = t & 1;         // each loads 16 consecutive k's

    for (int kc = 0; kc < K_ / KB_; kc++) {
        __syncthreads();
        // B tile: W1k rows kc*32..+31, contiguous in W1
        {
            const float4* src = (const float4*)(W1 + (size_t)kc * KB_ * HID_);
            float4* dst = (float4*)&sB[0][0];
            dst[t]       = src[t];
            dst[t + 256] = src[t + 256];
        }
        // A tile transposed: keys[p][kc*32 + half*16 + c] -> sA[half*16+c][p]
        {
            const float4* src = (const float4*)(keyb + (size_t)prow * K_ + kc * KB_ + half * 16);
            #pragma unroll
            for (int q = 0; q < 4; q++) {
                float4 v = src[q];
                int k0 = half * 16 + q * 4;
                sA[k0 + 0][prow] = v.x;
                sA[k0 + 1][prow] = v.y;
                sA[k0 + 2][prow] = v.z;
                sA[k0 + 3][prow] = v.w;
            }
        }
        __syncthreads();
        #pragma unroll 8
        for (int kk = 0; kk < KB_; kk++) {
            float4 b4 = *(const float4*)&sB[kk][tx * 4];
            float4 a0 = *(const float4*)&sA[kk][ty * 8];
            float4 a1 = *(const float4*)&sA[kk][ty * 8 + 4];
            float av[8] = {a0.x, a0.y, a0.z, a0.w, a1.x, a1.y, a1.z, a1.w};
            float bv[4] = {b4.x, b4.y, b4.z, b4.w};
            #pragma unroll
            for (int i = 0; i < 8; i++)
                #pragma unroll
                for (int j = 0; j < 4; j++)
                    acc[i][j] = fmaf(av[i], bv[j], acc[i][j]);
        }
    }

    // ---- relu(acc + qf) @ W2, reduce across the 16 tx lanes ----
    #pragma unroll
    for (int i = 0; i < 8; i++) {
        float s = 0.f;
        #pragma unroll
        for (int j = 0; j < 4; j++) {
            float hv = acc[i][j] + sQF[tx * 4 + j];
            hv = fmaxf(hv, 0.f);
            s = fmaf(hv, sW2[tx * 4 + j], s);
        }
        #pragma unroll
        for (int off = 8; off >= 1; off >>= 1)
            s += __shfl_xor_sync(0xffffffffu, s, off);
        if (tx == 0) sScore[ty * 8 + i] = s;
    }
    __syncthreads();

    // ---- masked softmax over P (one warp) ----
    if (t < 32) {
        int   mk[4];
        float sc[4], e[4];
        float mx = -FLT_MAX;
        #pragma unroll
        for (int i = 0; i < 4; i++) {
            int p = t + 32 * i;
            mk[i] = mask[b * P_ + p];
            sc[i] = sScore[p];
            if (mk[i]) mx = fmaxf(mx, sc[i]);
        }
        #pragma unroll
        for (int off = 16; off >= 1; off >>= 1)
            mx = fmaxf(mx, __shfl_xor_sync(0xffffffffu, mx, off));
        float sum = 0.f;
        #pragma unroll
        for (int i = 0; i < 4; i++) {
            e[i] = mk[i] ? __expf(sc[i] - mx) : 0.f;
            sum += e[i];
        }
        #pragma unroll
        for (int off = 16; off >= 1; off >>= 1)
            sum += __shfl_xor_sync(0xffffffffu, sum, off);
        float inv = 1.0f / sum;
        #pragma unroll
        for (int i = 0; i < 4; i++) {
            int p = t + 32 * i;
            float w = e[i] * inv;
            sScore[p] = w;
            out[(size_t)B_ * EMB_ + (size_t)b * P_ + p] = w;   // weights output
        }
    }
    __syncthreads();

    // ---- context = weights @ keys ; embeddings = [context | frame] ----
    {
        float c0 = 0.f, c1 = 0.f;
        #pragma unroll 4
        for (int p = 0; p < P_; p++) {
            float w = sScore[p];
            c0 = fmaf(w, keyb[(size_t)p * K_ + t],       c0);
            c1 = fmaf(w, keyb[(size_t)p * K_ + t + 256], c1);
        }
        float* eb = out + (size_t)b * EMB_;
        eb[t]       = c0;
        eb[t + 256] = c1;
        #pragma unroll
        for (int i = 0; i < 4; i++)
            eb[K_ + t + 256 * i] = fb[t + 256 * i];
    }
}

extern "C" void kernel_launch(void* const* d_in, const int* in_sizes, int n_in,
                              void* d_out, int out_size) {
    const float* query = (const float*)d_in[0];
    const float* keys  = (const float*)d_in[1];
    const float* frame = (const float*)d_in[2];
    const int*   mask  = (const int*)d_in[3];
    const float* W1    = (const float*)d_in[4];
    const float* W2    = (const float*)d_in[5];
    float* out = (float*)d_out;

    attn_fused<<<B_, 256>>>(query, keys, frame, mask, W1, W2, out);
}

// round 3
// speedup vs baseline: 1.3581x; 1.3581x over previous
#include <cuda_runtime.h>
#include <cuda_bf16.h>
#include <mma.h>
#include <cstdint>
#include <cfloat>

using namespace nvcuda;

#define B_   256
#define P_   128
#define K_   512
#define HID_ 64
#define EMB_ 1536   // K_ + 1024 (frame)

// ---------------- scratch: qf partials ----------------
__device__ float g_qfp[8][B_][HID_];   // [d-slice][batch][h]

// ---------------- kernel 1: qf = [query|frame] @ W1[qf] ----------------
// grid 256 = (bg 0..31) x (ds 0..7); 256 threads
__global__ __launch_bounds__(256, 4)
void qf_kernel(const float* __restrict__ query,
               const float* __restrict__ frame,
               const float* __restrict__ W1) {
    __shared__ float sX[8][256];
    const int bg = blockIdx.x & 31;
    const int ds = blockIdx.x >> 5;
    const int t  = threadIdx.x;

    const float* src = (ds < 4) ? (query + ds * 256) : (frame + (ds - 4) * 256);
    #pragma unroll
    for (int j = 0; j < 8; j++) {
        int lin = j * 256 + t;
        int bb = lin >> 8, ff = lin & 255;
        sX[bb][ff] = src[(size_t)(bg * 8 + bb) * 1024 + ff];
    }
    __syncthreads();

    const int h  = t & 63;
    const int bs = t >> 6;
    const float* w = W1 + (size_t)(K_ + ds * 256) * HID_ + h;
    float a0 = 0.f, a1 = 0.f;
    #pragma unroll 8
    for (int d = 0; d < 256; d++) {
        float wv = w[(size_t)d * HID_];
        a0 = fmaf(wv, sX[bs][d],     a0);
        a1 = fmaf(wv, sX[bs + 4][d], a1);
    }
    g_qfp[ds][bg * 8 + bs][h]     = a0;
    g_qfp[ds][bg * 8 + bs + 4][h] = a1;
}

// ---------------- kernel 2: main fused attention (wmma bf16 split) ----------------
// dynamic SMEM layout (bytes):
//   [0)      sAh : 128 x 72 bf16 = 18432        (aliased by sH after GEMM)
//   [18432)  sAl : 128 x 72 bf16 = 18432
//   [36864)  sBh :  64 x 72 bf16 =  9216
//   [46080)  sBl :  64 x 72 bf16 =  9216
//   [55296)  sQF 64f | [55552) sW2 64f | [55808) sScore 128f
#define OFF_AH 0u
#define OFF_AL 18432u
#define OFF_BH 36864u
#define OFF_BL 46080u
#define OFF_QF 55296u
#define OFF_W2 55552u
#define OFF_SC 55808u
#define SMEM_BYTES 56320
#define LDA 72
#define LDH 68   // sH (float) leading dim

__device__ __forceinline__ void split_bf16(float x, __nv_bfloat16& hi, __nv_bfloat16& lo) {
    hi = __float2bfloat16(x);
    lo = __float2bfloat16(x - __bfloat162float(hi));
}

__global__ __launch_bounds__(256, 2)
void attn_main(const float* __restrict__ keys,
               const float* __restrict__ frame,
               const int*   __restrict__ mask,
               const float* __restrict__ W1,
               const float* __restrict__ W2,
               float* __restrict__ out) {
    extern __shared__ char smem[];
    __nv_bfloat16* sAh = (__nv_bfloat16*)(smem + OFF_AH);
    __nv_bfloat16* sAl = (__nv_bfloat16*)(smem + OFF_AL);
    __nv_bfloat16* sBh = (__nv_bfloat16*)(smem + OFF_BH);
    __nv_bfloat16* sBl = (__nv_bfloat16*)(smem + OFF_BL);
    float* sQF    = (float*)(smem + OFF_QF);
    float* sW2    = (float*)(smem + OFF_W2);
    float* sScore = (float*)(smem + OFF_SC);
    float* sH     = (float*)(smem + OFF_AH);   // alias, used after GEMM

    const int b = blockIdx.x;
    const int t = threadIdx.x;
    const int wid = t >> 5;
    const float* keyb = keys  + (size_t)b * P_ * K_;
    const float* fb   = frame + (size_t)b * 1024;

    if (t < HID_) {
        float s = 0.f;
        #pragma unroll
        for (int ds = 0; ds < 8; ds++) s += g_qfp[ds][b][t];
        sQF[t] = s;
        sW2[t] = W2[t];
    }

    // ---- GEMM: H[128,64] = keys[b] @ W1k via wmma bf16, 3-term split ----
    wmma::fragment<wmma::accumulator, 16, 16, 16, float> acc[4];
    #pragma unroll
    for (int n = 0; n < 4; n++) wmma::fill_fragment(acc[n], 0.f);

    const int arow = wid * 16;

    for (int kc = 0; kc < 8; kc++) {          // 8 chunks of Kc=64
        __syncthreads();                       // tiles free (prev compute done)
        // stage A: keys[p][kc*64 + c], 128x64 fp32 -> bf16 hi/lo
        #pragma unroll
        for (int i = 0; i < 8; i++) {
            int f4i = t + 256 * i;
            int row = f4i >> 4;
            int c4  = f4i & 15;
            float4 v = *(const float4*)(keyb + (size_t)row * K_ + kc * 64 + c4 * 4);
            __nv_bfloat16 h0,l0,h1,l1,h2,l2,h3,l3;
            split_bf16(v.x, h0, l0); split_bf16(v.y, h1, l1);
            split_bf16(v.z, h2, l2); split_bf16(v.w, h3, l3);
            int eo = row * LDA + c4 * 4;
            *(__nv_bfloat162*)(sAh + eo)     = __nv_bfloat162(h0, h1);
            *(__nv_bfloat162*)(sAh + eo + 2) = __nv_bfloat162(h2, h3);
            *(__nv_bfloat162*)(sAl + eo)     = __nv_bfloat162(l0, l1);
            *(__nv_bfloat162*)(sAl + eo + 2) = __nv_bfloat162(l2, l3);
        }
        // stage B: W1k[kc*64 + r][n], 64x64 fp32 -> bf16 hi/lo
        #pragma unroll
        for (int i = 0; i < 4; i++) {
            int f4i = t + 256 * i;
            int row = f4i >> 4;
            int c4  = f4i & 15;
            float4 v = *(const float4*)(W1 + (size_t)(kc * 64 + row) * HID_ + c4 * 4);
            __nv_bfloat16 h0,l0,h1,l1,h2,l2,h3,l3;
            split_bf16(v.x, h0, l0); split_bf16(v.y, h1, l1);
            split_bf16(v.z, h2, l2); split_bf16(v.w, h3, l3);
            int eo = row * LDA + c4 * 4;
            *(__nv_bfloat162*)(sBh + eo)     = __nv_bfloat162(h0, h1);
            *(__nv_bfloat162*)(sBh + eo + 2) = __nv_bfloat162(h2, h3);
            *(__nv_bfloat162*)(sBl + eo)     = __nv_bfloat162(l0, l1);
            *(__nv_bfloat162*)(sBl + eo + 2) = __nv_bfloat162(l2, l3);
        }
        __syncthreads();

        #pragma unroll
        for (int ks = 0; ks < 4; ks++) {       // 4 sub-chunks of k16
            wmma::fragment<wmma::matrix_a, 16, 16, 16, __nv_bfloat16, wmma::row_major> ah, al;
            wmma::load_matrix_sync(ah, sAh + arow * LDA + ks * 16, LDA);
            wmma::load_matrix_sync(al, sAl + arow * LDA + ks * 16, LDA);
            #pragma unroll
            for (int n = 0; n < 4; n++) {
                wmma::fragment<wmma::matrix_b, 16, 16, 16, __nv_bfloat16, wmma::row_major> bh, bl;
                wmma::load_matrix_sync(bh, sBh + (ks * 16) * LDA + n * 16, LDA);
                wmma::load_matrix_sync(bl, sBl + (ks * 16) * LDA + n * 16, LDA);
                wmma::mma_sync(acc[n], ah, bh, acc[n]);
                wmma::mma_sync(acc[n], ah, bl, acc[n]);
                wmma::mma_sync(acc[n], al, bh, acc[n]);
            }
        }
    }

    __syncthreads();   // all tile reads done before sH aliases the region
    #pragma unroll
    for (int n = 0; n < 4; n++)
        wmma::store_matrix_sync(sH + arow * LDH + n * 16, acc[n], LDH, wmma::mem_row_major);
    __syncthreads();

    // ---- scores: relu(H + qf) . W2 ----
    if (t < P_) {
        float sc = 0.f;
        const float* hr = sH + t * LDH;
        #pragma unroll
        for (int j = 0; j < HID_; j++) {
            float hv = hr[j] + sQF[j];
            sc = fmaf(fmaxf(hv, 0.f), sW2[j], sc);
        }
        sScore[t] = sc;
    }
    __syncthreads();

    // ---- masked softmax over P (one warp) ----
    if (t < 32) {
        int   mk[4];
        float scv[4], e[4];
        float mx = -FLT_MAX;
        #pragma unroll
        for (int i = 0; i < 4; i++) {
            int p = t + 32 * i;
            mk[i]  = mask[b * P_ + p];
            scv[i] = sScore[p];
            if (mk[i]) mx = fmaxf(mx, scv[i]);
        }
        #pragma unroll
        for (int off = 16; off >= 1; off >>= 1)
            mx = fmaxf(mx, __shfl_xor_sync(0xffffffffu, mx, off));
        float sum = 0.f;
        #pragma unroll
        for (int i = 0; i < 4; i++) { e[i] = mk[i] ? __expf(scv[i] - mx) : 0.f; sum += e[i]; }
        #pragma unroll
        for (int off = 16; off >= 1; off >>= 1)
            sum += __shfl_xor_sync(0xffffffffu, sum, off);
        float inv = 1.0f / sum;
        #pragma unroll
        for (int i = 0; i < 4; i++) {
            int p = t + 32 * i;
            float w = e[i] * inv;
            sScore[p] = w;
            out[(size_t)B_ * EMB_ + (size_t)b * P_ + p] = w;
        }
    }
    __syncthreads();

    // ---- context = weights @ keys ; embeddings = [context | frame] ----
    {
        float c0 = 0.f, c1 = 0.f;
        #pragma unroll 4
        for (int p = 0; p < P_; p++) {
            float w = sScore[p];
            c0 = fmaf(w, keyb[(size_t)p * K_ + t],       c0);
            c1 = fmaf(w, keyb[(size_t)p * K_ + t + 256], c1);
        }
        float* eb = out + (size_t)b * EMB_;
        eb[t]       = c0;
        eb[t + 256] = c1;
        #pragma unroll
        for (int i = 0; i < 4; i++)
            eb[K_ + t + 256 * i] = fb[t + 256 * i];
    }
}

extern "C" void kernel_launch(void* const* d_in, const int* in_sizes, int n_in,
                              void* d_out, int out_size) {
    const float* query = (const float*)d_in[0];
    const float* keys  = (const float*)d_in[1];
    const float* frame = (const float*)d_in[2];
    const int*   mask  = (const int*)d_in[3];
    const float* W1    = (const float*)d_in[4];
    const float* W2    = (const float*)d_in[5];
    float* out = (float*)d_out;

    static int cfg_done = 0;
    if (!cfg_done) {
        cudaFuncSetAttribute(attn_main, cudaFuncAttributeMaxDynamicSharedMemorySize, SMEM_BYTES);
        cfg_done = 1;
    }

    qf_kernel<<<256, 256>>>(query, frame, W1);
    attn_main<<<B_, 256, SMEM_BYTES>>>(keys, frame, mask, W1, W2, out);
}

// round 4
// speedup vs baseline: 1.5945x; 1.1741x over previous
#include <cuda_runtime.h>
#include <cuda_bf16.h>
#include <mma.h>
#include <cstdint>
#include <cfloat>

using namespace nvcuda;

#define B_   256
#define P_   128
#define K_   512
#define HID_ 64
#define EMB_ 1536   // K_ + 1024 (frame)

// ---------------- scratch: qf partials ----------------
__device__ float g_qfp[8][B_][HID_];   // [d-slice][batch][h]

// ---------------- kernel 1: qf = [query|frame] @ W1[qf] ----------------
__global__ __launch_bounds__(256, 4)
void qf_kernel(const float* __restrict__ query,
               const float* __restrict__ frame,
               const float* __restrict__ W1) {
    __shared__ float sX[8][256];
    const int bg = blockIdx.x & 31;
    const int ds = blockIdx.x >> 5;
    const int t  = threadIdx.x;

    const float* src = (ds < 4) ? (query + ds * 256) : (frame + (ds - 4) * 256);
    #pragma unroll
    for (int j = 0; j < 8; j++) {
        int lin = j * 256 + t;
        int bb = lin >> 8, ff = lin & 255;
        sX[bb][ff] = src[(size_t)(bg * 8 + bb) * 1024 + ff];
    }
    __syncthreads();

    const int h  = t & 63;
    const int bs = t >> 6;
    const float* w = W1 + (size_t)(K_ + ds * 256) * HID_ + h;
    float a0 = 0.f, a1 = 0.f;
    #pragma unroll 8
    for (int d = 0; d < 256; d++) {
        float wv = w[(size_t)d * HID_];
        a0 = fmaf(wv, sX[bs][d],     a0);
        a1 = fmaf(wv, sX[bs + 4][d], a1);
    }
    g_qfp[ds][bg * 8 + bs][h]     = a0;
    g_qfp[ds][bg * 8 + bs + 4][h] = a1;
}

// ---------------- kernel 2: main fused attention ----------------
// SMEM layout (bytes):
//   [0)      sAh : 128 x 72 bf16 = 18432   (aliased by sH after GEMM)
//   [18432)  sAl : 128 x 72 bf16 = 18432
//   [36864)  sBh :  64 x 72 bf16 =  9216
//   [46080)  sBl :  64 x 72 bf16 =  9216
//   [55296)  sQF 64f | [55552) sW2 64f | [55808) sScore 128f
#define OFF_AH 0u
#define OFF_AL 18432u
#define OFF_BH 36864u
#define OFF_BL 46080u
#define OFF_QF 55296u
#define OFF_W2 55552u
#define OFF_SC 55808u
#define SMEM_BYTES 56320
#define LDA 72
#define LDH 68

union PackB4 { __nv_bfloat16 b[4]; uint2 u; };

__device__ __forceinline__ void split4(float4 v, PackB4& hi, PackB4& lo) {
    #pragma unroll
    for (int q = 0; q < 4; q++) {
        float x = (q == 0) ? v.x : (q == 1) ? v.y : (q == 2) ? v.z : v.w;
        __nv_bfloat16 h = __float2bfloat16(x);
        hi.b[q] = h;
        lo.b[q] = __float2bfloat16(x - __bfloat162float(h));
    }
}

__global__ __launch_bounds__(256, 2)
void attn_main(const float* __restrict__ keys,
               const float* __restrict__ frame,
               const int*   __restrict__ mask,
               const float* __restrict__ W1,
               const float* __restrict__ W2,
               float* __restrict__ out) {
    extern __shared__ char smem[];
    __nv_bfloat16* sAh = (__nv_bfloat16*)(smem + OFF_AH);
    __nv_bfloat16* sAl = (__nv_bfloat16*)(smem + OFF_AL);
    __nv_bfloat16* sBh = (__nv_bfloat16*)(smem + OFF_BH);
    __nv_bfloat16* sBl = (__nv_bfloat16*)(smem + OFF_BL);
    float* sQF    = (float*)(smem + OFF_QF);
    float* sW2    = (float*)(smem + OFF_W2);
    float* sScore = (float*)(smem + OFF_SC);
    float* sH     = (float*)(smem + OFF_AH);   // alias after GEMM

    const int b = blockIdx.x;
    const int t = threadIdx.x;
    const int wid = t >> 5;
    const float* keyb = keys  + (size_t)b * P_ * K_;
    const float* fb   = frame + (size_t)b * 1024;

    // staging geometry (A: 8 float4/thread, B: 4 float4/thread)
    const int arow = t >> 4;          // base row (of 16-row groups), +16 per i
    const int ac4  = t & 15;          // float4 column within 64-col chunk

    // ---- prologue: prefetch A chunk 0 into registers ----
    float4 ra[8];
    #pragma unroll
    for (int i = 0; i < 8; i++)
        ra[i] = *(const float4*)(keyb + (size_t)(arow + 16 * i) * K_ + ac4 * 4);

    if (t < HID_) {
        float s = 0.f;
        #pragma unroll
        for (int ds = 0; ds < 8; ds++) s += g_qfp[ds][b][t];
        sQF[t] = s;
        sW2[t] = W2[t];
    }

    // ---- GEMM: H[128,64] = keys[b] @ W1k, wmma bf16 3-term split ----
    // warp tiling 4M x 2N: warp owns rows wm*32..+31, cols wn*32..+31
    const int wm = wid & 3;
    const int wn = wid >> 2;
    wmma::fragment<wmma::accumulator, 16, 16, 16, float> acc[2][2];
    #pragma unroll
    for (int i = 0; i < 2; i++)
        #pragma unroll
        for (int j = 0; j < 2; j++) wmma::fill_fragment(acc[i][j], 0.f);

    for (int kc = 0; kc < 8; kc++) {
        // stage B (synchronous; W1k is L2-resident across CTAs)
        #pragma unroll
        for (int i = 0; i < 4; i++) {
            int row = arow + 16 * i;      // 0..63
            float4 v = *(const float4*)(W1 + (size_t)(kc * 64 + row) * HID_ + ac4 * 4);
            PackB4 hi, lo; split4(v, hi, lo);
            int eo = row * LDA + ac4 * 4;
            *(uint2*)(sBh + eo) = hi.u;
            *(uint2*)(sBl + eo) = lo.u;
        }
        // stage A from prefetched registers
        #pragma unroll
        for (int i = 0; i < 8; i++) {
            PackB4 hi, lo; split4(ra[i], hi, lo);
            int eo = (arow + 16 * i) * LDA + ac4 * 4;
            *(uint2*)(sAh + eo) = hi.u;
            *(uint2*)(sAl + eo) = lo.u;
        }
        __syncthreads();   // tiles ready

        // prefetch next A chunk (flies under the MMA phase)
        if (kc < 7) {
            #pragma unroll
            for (int i = 0; i < 8; i++)
                ra[i] = *(const float4*)(keyb + (size_t)(arow + 16 * i) * K_ + (kc + 1) * 64 + ac4 * 4);
        }

        #pragma unroll
        for (int ks = 0; ks < 4; ks++) {
            wmma::fragment<wmma::matrix_a, 16, 16, 16, __nv_bfloat16, wmma::row_major> ah[2], al[2];
            #pragma unroll
            for (int i = 0; i < 2; i++) {
                wmma::load_matrix_sync(ah[i], sAh + (wm * 32 + i * 16) * LDA + ks * 16, LDA);
                wmma::load_matrix_sync(al[i], sAl + (wm * 32 + i * 16) * LDA + ks * 16, LDA);
            }
            #pragma unroll
            for (int nf = 0; nf < 2; nf++) {
                wmma::fragment<wmma::matrix_b, 16, 16, 16, __nv_bfloat16, wmma::row_major> bh, bl;
                wmma::load_matrix_sync(bh, sBh + (ks * 16) * LDA + wn * 32 + nf * 16, LDA);
                wmma::load_matrix_sync(bl, sBl + (ks * 16) * LDA + wn * 32 + nf * 16, LDA);
                #pragma unroll
                for (int i = 0; i < 2; i++) {
                    wmma::mma_sync(acc[i][nf], ah[i], bh, acc[i][nf]);
                    wmma::mma_sync(acc[i][nf], ah[i], bl, acc[i][nf]);
                    wmma::mma_sync(acc[i][nf], al[i], bh, acc[i][nf]);
                }
            }
        }
        __syncthreads();   // tiles consumed
    }

    #pragma unroll
    for (int i = 0; i < 2; i++)
        #pragma unroll
        for (int j = 0; j < 2; j++)
            wmma::store_matrix_sync(sH + (wm * 32 + i * 16) * LDH + wn * 32 + j * 16,
                                    acc[i][j], LDH, wmma::mem_row_major);
    __syncthreads();

    // ---- scores: relu(H + qf) . W2 ----
    if (t < P_) {
        float sc = 0.f;
        const float* hr = sH + t * LDH;
        #pragma unroll
        for (int j = 0; j < HID_; j++) {
            float hv = hr[j] + sQF[j];
            sc = fmaf(fmaxf(hv, 0.f), sW2[j], sc);
        }
        sScore[t] = sc;
    }
    __syncthreads();

    // ---- masked softmax over P (one warp) ----
    if (t < 32) {
        int   mk[4];
        float scv[4], e[4];
        float mx = -FLT_MAX;
        #pragma unroll
        for (int i = 0; i < 4; i++) {
            int p = t + 32 * i;
            mk[i]  = mask[b * P_ + p];
            scv[i] = sScore[p];
            if (mk[i]) mx = fmaxf(mx, scv[i]);
        }
        #pragma unroll
        for (int off = 16; off >= 1; off >>= 1)
            mx = fmaxf(mx, __shfl_xor_sync(0xffffffffu, mx, off));
        float sum = 0.f;
        #pragma unroll
        for (int i = 0; i < 4; i++) { e[i] = mk[i] ? __expf(scv[i] - mx) : 0.f; sum += e[i]; }
        #pragma unroll
        for (int off = 16; off >= 1; off >>= 1)
            sum += __shfl_xor_sync(0xffffffffu, sum, off);
        float inv = 1.0f / sum;
        #pragma unroll
        for (int i = 0; i < 4; i++) {
            int p = t + 32 * i;
            float w = e[i] * inv;
            sScore[p] = w;
            out[(size_t)B_ * EMB_ + (size_t)b * P_ + p] = w;
        }
    }
    __syncthreads();

    // ---- context = weights @ keys (4 independent chains, 16 loads in flight) ----
    {
        float c0 = 0.f, c1 = 0.f, d0 = 0.f, d1 = 0.f;
        #pragma unroll 4
        for (int p = 0; p < P_; p += 2) {
            float wa = sScore[p];
            float wb = sScore[p + 1];
            c0 = fmaf(wa, keyb[(size_t)p * K_ + t],             c0);
            c1 = fmaf(wa, keyb[(size_t)p * K_ + t + 256],       c1);
            d0 = fmaf(wb, keyb[(size_t)(p + 1) * K_ + t],       d0);
            d1 = fmaf(wb, keyb[(size_t)(p + 1) * K_ + t + 256], d1);
        }
        float* eb = out + (size_t)b * EMB_;
        eb[t]       = c0 + d0;
        eb[t + 256] = c1 + d1;
        #pragma unroll
        for (int i = 0; i < 4; i++)
            eb[K_ + t + 256 * i] = fb[t + 256 * i];
    }
}

extern "C" void kernel_launch(void* const* d_in, const int* in_sizes, int n_in,
                              void* d_out, int out_size) {
    const float* query = (const float*)d_in[0];
    const float* keys  = (const float*)d_in[1];
    const float* frame = (const float*)d_in[2];
    const int*   mask  = (const int*)d_in[3];
    const float* W1    = (const float*)d_in[4];
    const float* W2    = (const float*)d_in[5];
    float* out = (float*)d_out;

    static int cfg_done = 0;
    if (!cfg_done) {
        cudaFuncSetAttribute(attn_main, cudaFuncAttributeMaxDynamicSharedMemorySize, SMEM_BYTES);
        cfg_done = 1;
    }

    qf_kernel<<<256, 256>>>(query, frame, W1);
    attn_main<<<B_, 256, SMEM_BYTES>>>(keys, frame, mask, W1, W2, out);
}